// round 12
// baseline (speedup 1.0000x reference)
#include <cuda_runtime.h>
#include <cuda_bf16.h>

#define FEAT 128
#define RV (FEAT / 4)          // 32 float4 per row
#define NUM_GRAPHS 10000

// ---------------------------------------------------------------------------
// Zero the output (harness poisons d_out with 0xAA; atomics need zeros).
// ---------------------------------------------------------------------------
__global__ void zero_kernel(float4* __restrict__ out, int n4) {
    int i = blockIdx.x * blockDim.x + threadIdx.x;
    if (i < n4) out[i] = make_float4(0.f, 0.f, 0.f, 0.f);
}

__device__ __forceinline__ void flush_seg(float* __restrict__ out, int g,
                                          int lane, const float4& a) {
    float* o = out + (long long)g * FEAT + lane * 4;
    atomicAdd(o + 0, a.x);
    atomicAdd(o + 1, a.y);
    atomicAdd(o + 2, a.z);
    atomicAdd(o + 3, a.w);
}

// ---------------------------------------------------------------------------
// Sorted segment-sum, balanced warp chunks (aligned to 4 rows), rolling
// distance-4 register pipeline:
//   issue LDG.128 for row i+4+k, consume row i+k, rotate slot.
// Peak live data = 5 rows (20 regs) vs 8 rows for block double-buffering,
// fitting the <=42-reg budget for 48 warps/SM (6 blocks x 256 thr).
// Batch ids: one warp-uniform int4 per 4 rows. REDs only at boundaries.
// ---------------------------------------------------------------------------
__global__ __launch_bounds__(256, 6) void segsum_kernel(
    const float4* __restrict__ hv,     // h_t as [n_rows][32] float4
    const int* __restrict__ batch,     // sorted segment ids
    float* __restrict__ out,           // [NUM_GRAPHS][FEAT]
    int n_rows)
{
    const int lane        = threadIdx.x & 31;
    const int gwarp       = (blockIdx.x * blockDim.x + threadIdx.x) >> 5;
    const int total_warps = (gridDim.x * blockDim.x) >> 5;

    // 4-aligned balanced chunk; last warp absorbs the (4-aligned) remainder.
    int i = (int)(((long long)n_rows * gwarp) / total_warps) & ~3;
    int e = (gwarp == total_warps - 1)
              ? n_rows
              : ((int)(((long long)n_rows * (gwarp + 1)) / total_warps) & ~3);
    if (i >= e) return;

    const float4* p = hv + (long long)i * RV + lane;
    int    cur = batch[i];
    float4 acc = make_float4(0.f, 0.f, 0.f, 0.f);

#define CONSUME(bb, vv)                                                  \
    do {                                                                 \
        if ((bb) != cur) {                                               \
            flush_seg(out, cur, lane, acc);                              \
            cur = (bb);                                                  \
            acc = (vv);                                                  \
        } else {                                                         \
            acc.x += (vv).x; acc.y += (vv).y;                            \
            acc.z += (vv).z; acc.w += (vv).w;                            \
        }                                                                \
    } while (0)

    if (e - i >= 8) {
        // Prime: rows i..i+3 in flight.
        int4   B  = *(const int4*)(batch + i);          // uniform LDG.128
        float4 v0 = __ldcs(p + 0 * RV);
        float4 v1 = __ldcs(p + 1 * RV);
        float4 v2 = __ldcs(p + 2 * RV);
        float4 v3 = __ldcs(p + 3 * RV);

        while (e - i >= 8) {
            int4 C = *(const int4*)(batch + i + 4);     // uniform
            float4 w;
            w = __ldcs(p + 4 * RV); CONSUME(B.x, v0); v0 = w;
            w = __ldcs(p + 5 * RV); CONSUME(B.y, v1); v1 = w;
            w = __ldcs(p + 6 * RV); CONSUME(B.z, v2); v2 = w;
            w = __ldcs(p + 7 * RV); CONSUME(B.w, v3); v3 = w;
            B = C;
            p += 4 * RV;
            i += 4;
        }
        // Drain last primed group.
        CONSUME(B.x, v0); CONSUME(B.y, v1);
        CONSUME(B.z, v2); CONSUME(B.w, v3);
        p += 4 * RV;
        i += 4;
    }

    // Scalar tail (<8 rows chunks, or trailing rows).
    while (i < e) {
        float4 v = __ldcs(p);
        int    b = batch[i];
        CONSUME(b, v);
        p += RV;
        i++;
    }

    flush_seg(out, cur, lane, acc);
#undef CONSUME
}

// ---------------------------------------------------------------------------
// Harness entry point.
//   d_in[0] : h_t   float32 [N_NODES * FEAT]
//   d_in[1] : batch int32   [N_NODES]  (sorted)
//   d_out   : float32 [NUM_GRAPHS * FEAT]
// ---------------------------------------------------------------------------
extern "C" void kernel_launch(void* const* d_in, const int* in_sizes, int n_in,
                              void* d_out, int out_size) {
    const float4* hv    = (const float4*)d_in[0];
    const int*    batch = (const int*)d_in[1];
    float*        out   = (float*)d_out;
    const int n_rows = in_sizes[1];

    // 1) Zero the (poisoned) output.
    const int n4 = out_size / 4;
    zero_kernel<<<(n4 + 255) / 256, 256>>>((float4*)d_out, n4);

    // 2) Segment sum: 1776 blocks = 148 SMs x 6 resident x 2 exact waves,
    //    14208 warps x ~70 rows each.
    segsum_kernel<<<1776, 256>>>(hv, batch, out, n_rows);
}

// round 17
// speedup vs baseline: 1.0974x; 1.0974x over previous
#include <cuda_runtime.h>
#include <cuda_bf16.h>
#include <cuda_pipeline_primitives.h>

#define FEAT 128
#define RV (FEAT / 4)            // 32 float4 per row
#define NUM_GRAPHS 10000
#define STAGES 8                 // cp.async ring depth (rows in flight per warp)
#define WARPS_PER_BLOCK 8

// ---------------------------------------------------------------------------
// Zero the output (harness poisons d_out with 0xAA; atomics need zeros).
// ---------------------------------------------------------------------------
__global__ void zero_kernel(float4* __restrict__ out, int n4) {
    int i = blockIdx.x * blockDim.x + threadIdx.x;
    if (i < n4) out[i] = make_float4(0.f, 0.f, 0.f, 0.f);
}

__device__ __forceinline__ void flush_seg(float* __restrict__ out, int g,
                                          int lane, const float4& a) {
    float* o = out + (long long)g * FEAT + lane * 4;
    atomicAdd(o + 0, a.x);
    atomicAdd(o + 1, a.y);
    atomicAdd(o + 2, a.z);
    atomicAdd(o + 3, a.w);
}

// ---------------------------------------------------------------------------
// Sorted segment-sum, balanced warp chunks, cp.async SMEM ring.
// Each warp owns ~70 contiguous rows. It keeps STAGES rows in flight via
// LDGSTS into a private SMEM ring (one commit-group per row), consumes rows
// in order with LDS.128 + FADD4 + segment compare, and REDs only at segment
// boundaries. Depth is decoupled from the register file -> ~32 regs,
// 48 warps/SM, 8 rows outstanding per warp with uniform issue.
// ---------------------------------------------------------------------------
__global__ __launch_bounds__(256, 6) void segsum_kernel(
    const float4* __restrict__ hv,     // h_t as [n_rows][32] float4
    const int* __restrict__ batch,     // sorted segment ids
    float* __restrict__ out,           // [NUM_GRAPHS][FEAT]
    int n_rows)
{
    __shared__ float4 ring[WARPS_PER_BLOCK][STAGES][RV];   // 32 KB

    const int lane        = threadIdx.x & 31;
    const int warp_in_blk = threadIdx.x >> 5;
    const int gwarp       = (blockIdx.x * blockDim.x + threadIdx.x) >> 5;
    const int total_warps = (gridDim.x * blockDim.x) >> 5;

    const int s = (int)(((long long)n_rows * gwarp) / total_warps);
    const int e = (int)(((long long)n_rows * (gwarp + 1)) / total_warps);
    const int n = e - s;
    if (n <= 0) return;

    int    cur = batch[s];
    float4 acc = make_float4(0.f, 0.f, 0.f, 0.f);

#define CONSUME(bb, vv)                                                  \
    do {                                                                 \
        if ((bb) != cur) {                                               \
            flush_seg(out, cur, lane, acc);                              \
            cur = (bb);                                                  \
            acc = (vv);                                                  \
        } else {                                                         \
            acc.x += (vv).x; acc.y += (vv).y;                            \
            acc.z += (vv).z; acc.w += (vv).w;                            \
        }                                                                \
    } while (0)

    if (n > STAGES) {
        float4* myring = &ring[warp_in_blk][0][0];
        const float4* src = hv + (long long)s * RV + lane;

        // Prime: rows 0..STAGES-1 in flight, one commit group per row.
        #pragma unroll
        for (int k = 0; k < STAGES; k++) {
            __pipeline_memcpy_async(myring + k * RV + lane,
                                    src + (long long)k * RV, 16);
            __pipeline_commit();
        }

        for (int j = 0; j < n; j++) {
            __pipeline_wait_prior(STAGES - 1);     // row j's group complete
            const int slot = j & (STAGES - 1);
            float4 v = myring[slot * RV + lane];   // LDS.128, conflict-free
            CONSUME(batch[s + j], v);
            const int jn = j + STAGES;
            if (jn < n) {
                __pipeline_memcpy_async(myring + slot * RV + lane,
                                        src + (long long)jn * RV, 16);
            }
            __pipeline_commit();                   // commit every iter to keep
                                                   // group accounting uniform
        }
    } else {
        // Tiny chunk: plain scalar path.
        const float4* p = hv + (long long)s * RV + lane;
        for (int j = 0; j < n; j++, p += RV) {
            float4 v = __ldcs(p);
            CONSUME(batch[s + j], v);
        }
    }

    // Final flush (chunk may end mid-segment; neighbor shares it -> atomic).
    flush_seg(out, cur, lane, acc);
#undef CONSUME
}

// ---------------------------------------------------------------------------
// Harness entry point.
//   d_in[0] : h_t   float32 [N_NODES * FEAT]
//   d_in[1] : batch int32   [N_NODES]  (sorted)
//   d_out   : float32 [NUM_GRAPHS * FEAT]
// ---------------------------------------------------------------------------
extern "C" void kernel_launch(void* const* d_in, const int* in_sizes, int n_in,
                              void* d_out, int out_size) {
    const float4* hv    = (const float4*)d_in[0];
    const int*    batch = (const int*)d_in[1];
    float*        out   = (float*)d_out;
    const int n_rows = in_sizes[1];

    // 1) Zero the (poisoned) output.
    const int n4 = out_size / 4;
    zero_kernel<<<(n4 + 255) / 256, 256>>>((float4*)d_out, n4);

    // 2) Segment sum: 1776 blocks = 148 SMs x 6 resident x 2 exact waves,
    //    14208 warps x ~70 rows each, 8 rows in flight per warp via cp.async.
    segsum_kernel<<<1776, 256>>>(hv, batch, out, n_rows);
}